// round 1
// baseline (speedup 1.0000x reference)
#include <cuda_runtime.h>
#include <math.h>

#define Bc     8
#define Nc     1000
#define Ec     4
#define Dc     64
#define ADc    32
#define NEc    4000      // E * N
#define ACOLS  8000      // 2 * E * N

// Scratch (static device globals; no allocation)
__device__ float g_s[2][Bc][NEc][Dc];     // s_in / s_out   (16 MB)
__device__ float g_a[2][Bc][Nc][Dc];      // a_in / a_out   (4 MB)
__device__ float g_state[2][Bc][Nc][Dc];  // s1 / s2        (4 MB)

// ---------------------------------------------------------------------------
// s_in[b, e*N+n, f] = sum_d state[b,n,d] * W_in[e,f,d]   (and s_out with W_out)
// grid: B*N blocks, 256 threads (e = t>>6, f = t&63)
// ---------------------------------------------------------------------------
__global__ void k_compute_s(const float* __restrict__ ext_state, int use_ext,
                            const float* __restrict__ W_in,
                            const float* __restrict__ W_out) {
    int bn = blockIdx.x;
    int b = bn / Nc, n = bn % Nc;
    __shared__ float st[Dc];
    int t = threadIdx.x;
    if (t < Dc) {
        st[t] = use_ext ? ext_state[(size_t)bn * Dc + t] : g_state[0][b][n][t];
    }
    __syncthreads();
    int e = t >> 6, f = t & 63;
    const float4* wi = (const float4*)(W_in  + ((size_t)(e * Dc + f) * Dc));
    const float4* wo = (const float4*)(W_out + ((size_t)(e * Dc + f) * Dc));
    float accI = 0.f, accO = 0.f;
#pragma unroll
    for (int d4 = 0; d4 < Dc / 4; d4++) {
        float4 a  = wi[d4];
        float4 c  = wo[d4];
        float4 s4 = *(const float4*)&st[d4 * 4];
        accI += a.x * s4.x + a.y * s4.y + a.z * s4.z + a.w * s4.w;
        accO += c.x * s4.x + c.y * s4.y + c.z * s4.z + c.w * s4.w;
    }
    int i = e * Nc + n;
    g_s[0][b][i][f] = accI;
    g_s[1][b][i][f] = accO;
}

// ---------------------------------------------------------------------------
// a_half[b,n,f] = sum_{m<4000} A[b, n, half*4000 + m] * s_half[b, m, f]
// grid (16, 2, 8): x=row block (64 rows), y=half, z=batch. 256 threads.
// Tile: C 64x64, smem A 64x16, smem S 16x64, thread microtile 4x4.
// ---------------------------------------------------------------------------
__global__ void k_biggemm(const float* __restrict__ A) {
    int rb = blockIdx.x, half = blockIdx.y, b = blockIdx.z;
    int row0 = rb * 64;
    const float* Ab = A + (size_t)b * Nc * ACOLS + (size_t)half * NEc;
    const float (*S)[Dc] = g_s[half][b];
    float (*C)[Dc] = g_a[half][b];

    __shared__ float a_sm[64][16];
    __shared__ float s_sm[16][64];

    int t  = threadIdx.x;
    int lr = t >> 2;          // A-load row 0..63
    int lk = (t & 3) * 4;     // A-load k offset (float4)
    int sk = t >> 4;          // S-load k 0..15
    int sf = (t & 15) * 4;    // S-load f offset (float4)
    int ty = t >> 4, tx = t & 15;

    float4 aref, sref;
    {
        int grow = row0 + lr;
        if (grow < Nc) aref = *(const float4*)&Ab[(size_t)grow * ACOLS + lk];
        else           aref = make_float4(0.f, 0.f, 0.f, 0.f);
        sref = *(const float4*)&S[sk][sf];
    }

    float acc[4][4];
#pragma unroll
    for (int r = 0; r < 4; r++)
#pragma unroll
        for (int c = 0; c < 4; c++) acc[r][c] = 0.f;

    for (int kt = 0; kt < NEc; kt += 16) {
        *(float4*)&a_sm[lr][lk] = aref;
        *(float4*)&s_sm[sk][sf] = sref;
        __syncthreads();

        int ktn = kt + 16;
        if (ktn < NEc) {
            int grow = row0 + lr;
            if (grow < Nc) aref = *(const float4*)&Ab[(size_t)grow * ACOLS + ktn + lk];
            else           aref = make_float4(0.f, 0.f, 0.f, 0.f);
            sref = *(const float4*)&S[ktn + sk][sf];
        }

#pragma unroll
        for (int k = 0; k < 16; k++) {
            float4 sv = *(float4*)&s_sm[k][tx * 4];
            float av[4];
#pragma unroll
            for (int r = 0; r < 4; r++) av[r] = a_sm[ty * 4 + r][k];
#pragma unroll
            for (int r = 0; r < 4; r++) {
                acc[r][0] += av[r] * sv.x;
                acc[r][1] += av[r] * sv.y;
                acc[r][2] += av[r] * sv.z;
                acc[r][3] += av[r] * sv.w;
            }
        }
        __syncthreads();
    }

#pragma unroll
    for (int r = 0; r < 4; r++) {
        int grow = row0 + ty * 4 + r;
        if (grow < Nc) {
            float4 v = make_float4(acc[r][0], acc[r][1], acc[r][2], acc[r][3]);
            *(float4*)&C[grow][tx * 4] = v;
        }
    }
}

// ---------------------------------------------------------------------------
// GRU update. a = [a_in | a_out | state] (192)
// r = sigm(a @ Wr^T); z = sigm(a @ Wz^T)
// h = tanh([a_in|a_out|r*state] @ Wh^T); new = (1-z)*state + z*h
// grid: 8000/16 = 500 blocks, 256 threads (f = t&63, q = t>>6 -> 4 rows each)
// ---------------------------------------------------------------------------
__global__ void k_gru(const float* __restrict__ ext_state, int use_ext, int out_idx,
                      const float* __restrict__ W_r,
                      const float* __restrict__ W_z,
                      const float* __restrict__ W_h) {
    __shared__ float a_sm[16][192];
    __shared__ float rs_sm[16][64];
    int t = threadIdx.x;
    int base = blockIdx.x * 16;

    // cooperative load: 16 rows x 192 floats = 768 float4 / 4 = wait: 3072 floats
#pragma unroll
    for (int c = 0; c < 3; c++) {
        int idx = c * 256 + t;        // 0..767 (float4 granularity)
        int lr  = idx / 48;           // 0..15
        int j4  = idx % 48;           // 0..47
        int bn  = base + lr;
        int b = bn / Nc, n = bn % Nc;
        float4 v;
        if (j4 < 16)      v = *(const float4*)&g_a[0][b][n][j4 * 4];
        else if (j4 < 32) v = *(const float4*)&g_a[1][b][n][(j4 - 16) * 4];
        else {
            const float* sp = use_ext ? (ext_state + (size_t)bn * Dc)
                                      : &g_state[0][b][n][0];
            v = *(const float4*)&sp[(j4 - 32) * 4];
        }
        *(float4*)&a_sm[lr][j4 * 4] = v;
    }
    __syncthreads();

    int f = t & 63, q = t >> 6;
    const float4* Wr4 = (const float4*)(W_r + (size_t)f * 192);
    const float4* Wz4 = (const float4*)(W_z + (size_t)f * 192);
    const float4* Wh4 = (const float4*)(W_h + (size_t)f * 192);

    float pr[4] = {0, 0, 0, 0}, pz[4] = {0, 0, 0, 0}, h1[4] = {0, 0, 0, 0};

#pragma unroll 4
    for (int j4 = 0; j4 < 32; j4++) {       // j < 128: a_in/a_out segment
        float4 wr = Wr4[j4], wz = Wz4[j4], wh = Wh4[j4];
#pragma unroll
        for (int g = 0; g < 4; g++) {
            float4 av = *(float4*)&a_sm[q * 4 + g][j4 * 4];
            pr[g] += wr.x * av.x + wr.y * av.y + wr.z * av.z + wr.w * av.w;
            pz[g] += wz.x * av.x + wz.y * av.y + wz.z * av.z + wz.w * av.w;
            h1[g] += wh.x * av.x + wh.y * av.y + wh.z * av.z + wh.w * av.w;
        }
    }
#pragma unroll 4
    for (int j4 = 32; j4 < 48; j4++) {      // j in [128,192): state segment (r/z only)
        float4 wr = Wr4[j4], wz = Wz4[j4];
#pragma unroll
        for (int g = 0; g < 4; g++) {
            float4 av = *(float4*)&a_sm[q * 4 + g][j4 * 4];
            pr[g] += wr.x * av.x + wr.y * av.y + wr.z * av.z + wr.w * av.w;
            pz[g] += wz.x * av.x + wz.y * av.y + wz.z * av.z + wz.w * av.w;
        }
    }

#pragma unroll
    for (int g = 0; g < 4; g++) {
        float r = 1.f / (1.f + expf(-pr[g]));
        rs_sm[q * 4 + g][f] = r * a_sm[q * 4 + g][128 + f];
    }
    __syncthreads();

#pragma unroll 4
    for (int j4 = 0; j4 < 16; j4++) {       // h: r*state segment
        float4 wh = Wh4[32 + j4];
#pragma unroll
        for (int g = 0; g < 4; g++) {
            float4 rv = *(float4*)&rs_sm[q * 4 + g][j4 * 4];
            h1[g] += wh.x * rv.x + wh.y * rv.y + wh.z * rv.z + wh.w * rv.w;
        }
    }

#pragma unroll
    for (int g = 0; g < 4; g++) {
        int lr = q * 4 + g;
        int bn = base + lr;
        int b = bn / Nc, n = bn % Nc;
        float st = a_sm[lr][128 + f];
        float z  = 1.f / (1.f + expf(-pz[g]));
        float h  = tanhf(h1[g]);
        g_state[out_idx][b][n][f] = (1.f - z) * st + z * h;
    }
}

// ---------------------------------------------------------------------------
// out[b,n] = sum_f tanh( sum_{j<96} [s2|annot][j] * Wo1[f,j] ) * Wo2[f]
// grid: 8000/4 = 2000 blocks, 256 threads (4 rows x 64 f)
// ---------------------------------------------------------------------------
__global__ void k_final(const float* __restrict__ annotation,
                        const float* __restrict__ Wo1,
                        const float* __restrict__ Wo2,
                        float* __restrict__ out) {
    __shared__ float join[4][96];
    __shared__ float terms[4][64];
    int t = threadIdx.x;
    int base = blockIdx.x * 4;

    for (int idx = t; idx < 4 * 96; idx += 256) {
        int lr = idx / 96, j = idx % 96;
        int bn = base + lr;
        int b = bn / Nc, n = bn % Nc;
        join[lr][j] = (j < Dc) ? g_state[1][b][n][j]
                               : annotation[(size_t)bn * ADc + (j - Dc)];
    }
    __syncthreads();

    int f = t & 63, q = t >> 6;
    const float4* w = (const float4*)(Wo1 + (size_t)f * 96);
    float acc = 0.f;
#pragma unroll
    for (int j4 = 0; j4 < 24; j4++) {
        float4 wv = w[j4];
        float4 jv = *(float4*)&join[q][j4 * 4];
        acc += wv.x * jv.x + wv.y * jv.y + wv.z * jv.z + wv.w * jv.w;
    }
    terms[q][f] = tanhf(acc) * Wo2[f];
    __syncthreads();

    if (f == 0) {
        float s = 0.f;
#pragma unroll
        for (int i = 0; i < Dc; i++) s += terms[q][i];
        out[base + q] = s;
    }
}

// ---------------------------------------------------------------------------
extern "C" void kernel_launch(void* const* d_in, const int* in_sizes, int n_in,
                              void* d_out, int out_size) {
    const float* prop_state = (const float*)d_in[0];
    const float* annotation = (const float*)d_in[1];
    const float* A          = (const float*)d_in[2];
    const float* W_in       = (const float*)d_in[3];
    const float* W_out      = (const float*)d_in[4];
    const float* W_r        = (const float*)d_in[5];
    const float* W_z        = (const float*)d_in[6];
    const float* W_h        = (const float*)d_in[7];
    const float* Wo1        = (const float*)d_in[8];
    const float* Wo2        = (const float*)d_in[9];
    float* out = (float*)d_out;

    dim3 gemm_grid(16, 2, Bc);

    // ---- propagate step 1 (state = prop_state) ----
    k_compute_s<<<Bc * Nc, 256>>>(prop_state, 1, W_in, W_out);
    k_biggemm<<<gemm_grid, 256>>>(A);
    k_gru<<<Bc * Nc / 16, 256>>>(prop_state, 1, 0, W_r, W_z, W_h);

    // ---- propagate step 2 (state = g_state[0]) ----
    k_compute_s<<<Bc * Nc, 256>>>(nullptr, 0, W_in, W_out);
    k_biggemm<<<gemm_grid, 256>>>(A);
    k_gru<<<Bc * Nc / 16, 256>>>(nullptr, 0, 1, W_r, W_z, W_h);

    // ---- output head ----
    k_final<<<Bc * Nc / 4, 256>>>(annotation, Wo1, Wo2, out);
}

// round 2
// speedup vs baseline: 2.0130x; 2.0130x over previous
#include <cuda_runtime.h>
#include <math.h>

#define Bc     8
#define Nc     1000
#define Ec     4
#define Dc     64
#define ADc    32
#define NEc    4000      // E * N
#define ACOLS  8000      // 2 * E * N

// Scratch (static device globals; no allocation)
__device__ float g_s[2][Bc][NEc][Dc];     // s_in / s_out   (16 MB)
__device__ float g_a[2][Bc][Nc][Dc];      // a_in / a_out   (4 MB)
__device__ float g_state[2][Bc][Nc][Dc];  // s1 / s2        (4 MB)

__device__ __forceinline__ float to_tf32(float x) {
    float r;
    asm("cvt.rna.tf32.f32 %0, %1;" : "=f"(r) : "f"(x));
    return r;
}
__device__ __forceinline__ float4 to_tf32_4(float4 v) {
    v.x = to_tf32(v.x); v.y = to_tf32(v.y);
    v.z = to_tf32(v.z); v.w = to_tf32(v.w);
    return v;
}

// ---------------------------------------------------------------------------
// s projection as tiled GEMM:
//   out (8000 x 512) = X (8000 x 64) @ Wcat^T, Wcat = [W_in(256x64); W_out(256x64)]
//   col c: half=c>>8, e=(c>>6)&3, f=c&63 -> g_s[half][b][e*1000+n][f]
// grid (125, 8), block 256 (8 ty x 32 tx). Tile 64 rows x 64 cols, K=64.
// ---------------------------------------------------------------------------
__global__ void __launch_bounds__(256) k_compute_s2(
    const float* __restrict__ Xext, int use_ext,
    const float* __restrict__ W_in, const float* __restrict__ W_out) {
    const float* X = use_ext ? Xext : &g_state[0][0][0][0];
    int rb = blockIdx.x, cb = blockIdx.y;
    __shared__ float x_sm[64][64];
    __shared__ float wT[64][64];      // wT[k][c_local]
    int t = threadIdx.x;

    // load X tile 64x64 (rb*64 + 63 <= 7999, no predication)
#pragma unroll
    for (int i = 0; i < 4; i++) {
        int idx = i * 256 + t;
        int r = idx >> 4, c4 = idx & 15;
        int gr = rb * 64 + r;
        *(float4*)&x_sm[r][c4 * 4] = *(const float4*)&X[(size_t)gr * 64 + c4 * 4];
    }
    // load W tile, transposed into wT[k][c]
    const float* Wsrc = (cb < 4) ? (W_in + (size_t)cb * 64 * 64)
                                 : (W_out + (size_t)(cb - 4) * 64 * 64);
#pragma unroll
    for (int i = 0; i < 4; i++) {
        int idx = i * 256 + t;
        int cl = idx >> 4, k4 = idx & 15;
        float4 v = *(const float4*)&Wsrc[cl * 64 + k4 * 4];
        wT[k4 * 4 + 0][cl] = v.x;
        wT[k4 * 4 + 1][cl] = v.y;
        wT[k4 * 4 + 2][cl] = v.z;
        wT[k4 * 4 + 3][cl] = v.w;
    }
    __syncthreads();

    int ty = t >> 5, tx = t & 31;     // warp = single ty -> x reads broadcast
    float acc[8][2];
#pragma unroll
    for (int i = 0; i < 8; i++) { acc[i][0] = 0.f; acc[i][1] = 0.f; }

#pragma unroll
    for (int k4 = 0; k4 < 16; k4++) {
        float4 xv[8];
#pragma unroll
        for (int i = 0; i < 8; i++) xv[i] = *(float4*)&x_sm[ty * 8 + i][k4 * 4];
#pragma unroll
        for (int q = 0; q < 4; q++) {
            float2 wv = *(float2*)&wT[k4 * 4 + q][tx * 2];
#pragma unroll
            for (int i = 0; i < 8; i++) {
                float xs = (q == 0) ? xv[i].x : (q == 1) ? xv[i].y
                         : (q == 2) ? xv[i].z : xv[i].w;
                acc[i][0] += xs * wv.x;
                acc[i][1] += xs * wv.y;
            }
        }
    }

    int cbase = cb * 64 + tx * 2;
    int half = cbase >> 8, e = (cbase >> 6) & 3, f = cbase & 63;
#pragma unroll
    for (int i = 0; i < 8; i++) {
        int gr = rb * 64 + ty * 8 + i;
        int b = gr / 1000, n = gr % 1000;
        *(float2*)&g_s[half][b][e * 1000 + n][f] = make_float2(acc[i][0], acc[i][1]);
    }
}

// ---------------------------------------------------------------------------
// Big adjacency GEMM on TF32 tensor cores:
//   a_half[b] (1000 x 64) = A_half[b] (1000 x 4000) @ s_half[b] (4000 x 64)
// grid (16, 2, 8), block 128 (4 warps). Block tile 64x64, K tile 32.
// Warp w: rows w*16..w*16+15, all 64 cols via 8 n-tiles of m16n8k8.
// Double-buffered smem, register-staged global prefetch.
// Padded strides (36 / 72) -> conflict-free fragment LDS.
// ---------------------------------------------------------------------------
__global__ void __launch_bounds__(128) k_biggemm_tc(const float* __restrict__ A) {
    int rb = blockIdx.x, half = blockIdx.y, b = blockIdx.z;
    int row0 = rb * 64;
    const float* Ab = A + (size_t)b * Nc * ACOLS + (size_t)half * NEc;
    const float(*S)[Dc] = g_s[half][b];

    __shared__ float a_sm[2][64][36];
    __shared__ float s_sm[2][32][72];

    int t = threadIdx.x;
    int lane = t & 31, warp = t >> 5;
    int g = lane >> 2, tg = lane & 3;

    float acc[8][4];
#pragma unroll
    for (int nt = 0; nt < 8; nt++)
#pragma unroll
        for (int c = 0; c < 4; c++) acc[nt][c] = 0.f;

    // staging registers
    float4 aSt[4], sSt[4];
    int ar[4], ac4[4], sr[4], sc4[4];
#pragma unroll
    for (int i = 0; i < 4; i++) {
        int idx = i * 128 + t;
        ar[i] = idx >> 3; ac4[i] = idx & 7;     // A: 64 rows x 8 float4
        sr[i] = idx >> 4; sc4[i] = idx & 15;    // S: 32 rows x 16 float4
    }

    // prologue: load kt=0
#pragma unroll
    for (int i = 0; i < 4; i++) {
        int gr = row0 + ar[i];
        float4 v = make_float4(0.f, 0.f, 0.f, 0.f);
        if (gr < Nc) v = *(const float4*)&Ab[(size_t)gr * ACOLS + ac4[i] * 4];
        aSt[i] = to_tf32_4(v);
        sSt[i] = to_tf32_4(*(const float4*)&S[sr[i]][sc4[i] * 4]);
    }
#pragma unroll
    for (int i = 0; i < 4; i++) {
        *(float4*)&a_sm[0][ar[i]][ac4[i] * 4] = aSt[i];
        *(float4*)&s_sm[0][sr[i]][sc4[i] * 4] = sSt[i];
    }
    __syncthreads();

    int buf = 0;
    for (int kt = 0; kt < NEc; kt += 32) {
        int nkt = kt + 32;
        if (nkt < NEc) {
            // prefetch next K tile into registers
#pragma unroll
            for (int i = 0; i < 4; i++) {
                int gr = row0 + ar[i];
                float4 v = make_float4(0.f, 0.f, 0.f, 0.f);
                if (gr < Nc) v = *(const float4*)&Ab[(size_t)gr * ACOLS + nkt + ac4[i] * 4];
                aSt[i] = to_tf32_4(v);
                sSt[i] = to_tf32_4(*(const float4*)&S[nkt + sr[i]][sc4[i] * 4]);
            }
        }

        // compute on current buffer
        int wr = warp * 16;
#pragma unroll
        for (int kk = 0; kk < 4; kk++) {
            unsigned a0 = __float_as_uint(a_sm[buf][wr + g][kk * 8 + tg]);
            unsigned a1 = __float_as_uint(a_sm[buf][wr + g + 8][kk * 8 + tg]);
            unsigned a2 = __float_as_uint(a_sm[buf][wr + g][kk * 8 + tg + 4]);
            unsigned a3 = __float_as_uint(a_sm[buf][wr + g + 8][kk * 8 + tg + 4]);
#pragma unroll
            for (int nt = 0; nt < 8; nt++) {
                unsigned b0 = __float_as_uint(s_sm[buf][kk * 8 + tg][nt * 8 + g]);
                unsigned b1 = __float_as_uint(s_sm[buf][kk * 8 + tg + 4][nt * 8 + g]);
                asm volatile(
                    "mma.sync.aligned.m16n8k8.row.col.f32.tf32.tf32.f32 "
                    "{%0,%1,%2,%3},{%4,%5,%6,%7},{%8,%9},{%0,%1,%2,%3};"
                    : "+f"(acc[nt][0]), "+f"(acc[nt][1]),
                      "+f"(acc[nt][2]), "+f"(acc[nt][3])
                    : "r"(a0), "r"(a1), "r"(a2), "r"(a3), "r"(b0), "r"(b1));
            }
        }

        if (nkt < NEc) {
#pragma unroll
            for (int i = 0; i < 4; i++) {
                *(float4*)&a_sm[buf ^ 1][ar[i]][ac4[i] * 4] = aSt[i];
                *(float4*)&s_sm[buf ^ 1][sr[i]][sc4[i] * 4] = sSt[i];
            }
        }
        __syncthreads();
        buf ^= 1;
    }

    // epilogue
    float(*C)[Dc] = g_a[half][b];
    int r_a = row0 + warp * 16 + g;
    int r_b = r_a + 8;
#pragma unroll
    for (int nt = 0; nt < 8; nt++) {
        int col = nt * 8 + tg * 2;
        if (r_a < Nc) *(float2*)&C[r_a][col] = make_float2(acc[nt][0], acc[nt][1]);
        if (r_b < Nc) *(float2*)&C[r_b][col] = make_float2(acc[nt][2], acc[nt][3]);
    }
}

// ---------------------------------------------------------------------------
// GRU update. a = [a_in | a_out | state] (192)
// ---------------------------------------------------------------------------
__global__ void k_gru(const float* __restrict__ ext_state, int use_ext, int out_idx,
                      const float* __restrict__ W_r,
                      const float* __restrict__ W_z,
                      const float* __restrict__ W_h) {
    __shared__ float a_sm[16][192];
    __shared__ float rs_sm[16][64];
    int t = threadIdx.x;
    int base = blockIdx.x * 16;

#pragma unroll
    for (int c = 0; c < 3; c++) {
        int idx = c * 256 + t;        // 0..767 (float4 granularity)
        int lr  = idx / 48;           // 0..15
        int j4  = idx % 48;           // 0..47
        int bn  = base + lr;
        int b = bn / Nc, n = bn % Nc;
        float4 v;
        if (j4 < 16)      v = *(const float4*)&g_a[0][b][n][j4 * 4];
        else if (j4 < 32) v = *(const float4*)&g_a[1][b][n][(j4 - 16) * 4];
        else {
            const float* sp = use_ext ? (ext_state + (size_t)bn * Dc)
                                      : &g_state[0][b][n][0];
            v = *(const float4*)&sp[(j4 - 32) * 4];
        }
        *(float4*)&a_sm[lr][j4 * 4] = v;
    }
    __syncthreads();

    int f = t & 63, q = t >> 6;
    const float4* Wr4 = (const float4*)(W_r + (size_t)f * 192);
    const float4* Wz4 = (const float4*)(W_z + (size_t)f * 192);
    const float4* Wh4 = (const float4*)(W_h + (size_t)f * 192);

    float pr[4] = {0, 0, 0, 0}, pz[4] = {0, 0, 0, 0}, h1[4] = {0, 0, 0, 0};

#pragma unroll 4
    for (int j4 = 0; j4 < 32; j4++) {       // j < 128: a_in/a_out segment
        float4 wr = Wr4[j4], wz = Wz4[j4], wh = Wh4[j4];
#pragma unroll
        for (int g = 0; g < 4; g++) {
            float4 av = *(float4*)&a_sm[q * 4 + g][j4 * 4];
            pr[g] += wr.x * av.x + wr.y * av.y + wr.z * av.z + wr.w * av.w;
            pz[g] += wz.x * av.x + wz.y * av.y + wz.z * av.z + wz.w * av.w;
            h1[g] += wh.x * av.x + wh.y * av.y + wh.z * av.z + wh.w * av.w;
        }
    }
#pragma unroll 4
    for (int j4 = 32; j4 < 48; j4++) {      // j in [128,192): state segment (r/z only)
        float4 wr = Wr4[j4], wz = Wz4[j4];
#pragma unroll
        for (int g = 0; g < 4; g++) {
            float4 av = *(float4*)&a_sm[q * 4 + g][j4 * 4];
            pr[g] += wr.x * av.x + wr.y * av.y + wr.z * av.z + wr.w * av.w;
            pz[g] += wz.x * av.x + wz.y * av.y + wz.z * av.z + wz.w * av.w;
        }
    }

#pragma unroll
    for (int g = 0; g < 4; g++) {
        float r = 1.f / (1.f + expf(-pr[g]));
        rs_sm[q * 4 + g][f] = r * a_sm[q * 4 + g][128 + f];
    }
    __syncthreads();

#pragma unroll 4
    for (int j4 = 0; j4 < 16; j4++) {       // h: r*state segment
        float4 wh = Wh4[32 + j4];
#pragma unroll
        for (int g = 0; g < 4; g++) {
            float4 rv = *(float4*)&rs_sm[q * 4 + g][j4 * 4];
            h1[g] += wh.x * rv.x + wh.y * rv.y + wh.z * rv.z + wh.w * rv.w;
        }
    }

#pragma unroll
    for (int g = 0; g < 4; g++) {
        int lr = q * 4 + g;
        int bn = base + lr;
        int b = bn / Nc, n = bn % Nc;
        float st = a_sm[lr][128 + f];
        float z  = 1.f / (1.f + expf(-pz[g]));
        float h  = tanhf(h1[g]);
        g_state[out_idx][b][n][f] = (1.f - z) * st + z * h;
    }
}

// ---------------------------------------------------------------------------
// out[b,n] = sum_f tanh( sum_{j<96} [s2|annot][j] * Wo1[f,j] ) * Wo2[f]
// ---------------------------------------------------------------------------
__global__ void k_final(const float* __restrict__ annotation,
                        const float* __restrict__ Wo1,
                        const float* __restrict__ Wo2,
                        float* __restrict__ out) {
    __shared__ float join[4][96];
    __shared__ float terms[4][64];
    int t = threadIdx.x;
    int base = blockIdx.x * 4;

    for (int idx = t; idx < 4 * 96; idx += 256) {
        int lr = idx / 96, j = idx % 96;
        int bn = base + lr;
        int b = bn / Nc, n = bn % Nc;
        join[lr][j] = (j < Dc) ? g_state[1][b][n][j]
                               : annotation[(size_t)bn * ADc + (j - Dc)];
    }
    __syncthreads();

    int f = t & 63, q = t >> 6;
    const float4* w = (const float4*)(Wo1 + (size_t)f * 96);
    float acc = 0.f;
#pragma unroll
    for (int j4 = 0; j4 < 24; j4++) {
        float4 wv = w[j4];
        float4 jv = *(float4*)&join[q][j4 * 4];
        acc += wv.x * jv.x + wv.y * jv.y + wv.z * jv.z + wv.w * jv.w;
    }
    terms[q][f] = tanhf(acc) * Wo2[f];
    __syncthreads();

    if (f == 0) {
        float s = 0.f;
#pragma unroll
        for (int i = 0; i < Dc; i++) s += terms[q][i];
        out[base + q] = s;
    }
}

// ---------------------------------------------------------------------------
extern "C" void kernel_launch(void* const* d_in, const int* in_sizes, int n_in,
                              void* d_out, int out_size) {
    const float* prop_state = (const float*)d_in[0];
    const float* annotation = (const float*)d_in[1];
    const float* A          = (const float*)d_in[2];
    const float* W_in       = (const float*)d_in[3];
    const float* W_out      = (const float*)d_in[4];
    const float* W_r        = (const float*)d_in[5];
    const float* W_z        = (const float*)d_in[6];
    const float* W_h        = (const float*)d_in[7];
    const float* Wo1        = (const float*)d_in[8];
    const float* Wo2        = (const float*)d_in[9];
    float* out = (float*)d_out;

    dim3 s_grid(125, 8);
    dim3 gemm_grid(16, 2, Bc);

    // ---- propagate step 1 (state = prop_state) ----
    k_compute_s2<<<s_grid, 256>>>(prop_state, 1, W_in, W_out);
    k_biggemm_tc<<<gemm_grid, 128>>>(A);
    k_gru<<<Bc * Nc / 16, 256>>>(prop_state, 1, 0, W_r, W_z, W_h);

    // ---- propagate step 2 (state = g_state[0]) ----
    k_compute_s2<<<s_grid, 256>>>(nullptr, 0, W_in, W_out);
    k_biggemm_tc<<<gemm_grid, 128>>>(A);
    k_gru<<<Bc * Nc / 16, 256>>>(nullptr, 0, 1, W_r, W_z, W_h);

    // ---- output head ----
    k_final<<<Bc * Nc / 4, 256>>>(annotation, Wo1, Wo2, out);
}

// round 3
// speedup vs baseline: 2.8194x; 1.4006x over previous
#include <cuda_runtime.h>
#include <math.h>

#define Bc     8
#define Nc     1000
#define Ec     4
#define Dc     64
#define ADc    32
#define NEc    4000      // E * N
#define ACOLS  8000      // 2 * E * N
#define KT     32        // biggemm K tile
#define NKT    125       // 4000 / 32

// Scratch (static device globals; no allocation)
__device__ float g_s[2][Bc][NEc][Dc];     // s_in / s_out (tf32-rounded)
__device__ float g_a[2][Bc][Nc][Dc];      // a_in / a_out
__device__ float g_state[2][Bc][Nc][Dc];  // s1 / s2

__device__ __forceinline__ float to_tf32(float x) {
    float r;
    asm("cvt.rna.tf32.f32 %0, %1;" : "=f"(r) : "f"(x));
    return r;
}

__device__ __forceinline__ void cp_async16(unsigned dst, const void* src) {
    asm volatile("cp.async.cg.shared.global [%0], [%1], 16;\n"
                 :: "r"(dst), "l"(src));
}
__device__ __forceinline__ void cp_commit() {
    asm volatile("cp.async.commit_group;\n");
}
__device__ __forceinline__ void cp_wait1() {
    asm volatile("cp.async.wait_group 1;\n");
}

// ---------------------------------------------------------------------------
// s projection as tiled GEMM:
//   out (8000 x 512) = X (8000 x 64) @ Wcat^T, Wcat = [W_in(256x64); W_out(256x64)]
// Stores tf32-rounded values into g_s (consumed raw by tensor-core GEMM).
// ---------------------------------------------------------------------------
__global__ void __launch_bounds__(256) k_compute_s2(
    const float* __restrict__ Xext, int use_ext,
    const float* __restrict__ W_in, const float* __restrict__ W_out) {
    const float* X = use_ext ? Xext : &g_state[0][0][0][0];
    int rb = blockIdx.x, cb = blockIdx.y;
    __shared__ float x_sm[64][64];
    __shared__ float wT[64][64];      // wT[k][c_local]
    int t = threadIdx.x;

#pragma unroll
    for (int i = 0; i < 4; i++) {
        int idx = i * 256 + t;
        int r = idx >> 4, c4 = idx & 15;
        int gr = rb * 64 + r;
        *(float4*)&x_sm[r][c4 * 4] = *(const float4*)&X[(size_t)gr * 64 + c4 * 4];
    }
    const float* Wsrc = (cb < 4) ? (W_in + (size_t)cb * 64 * 64)
                                 : (W_out + (size_t)(cb - 4) * 64 * 64);
#pragma unroll
    for (int i = 0; i < 4; i++) {
        int idx = i * 256 + t;
        int cl = idx >> 4, k4 = idx & 15;
        float4 v = *(const float4*)&Wsrc[cl * 64 + k4 * 4];
        wT[k4 * 4 + 0][cl] = v.x;
        wT[k4 * 4 + 1][cl] = v.y;
        wT[k4 * 4 + 2][cl] = v.z;
        wT[k4 * 4 + 3][cl] = v.w;
    }
    __syncthreads();

    int ty = t >> 5, tx = t & 31;
    float acc[8][2];
#pragma unroll
    for (int i = 0; i < 8; i++) { acc[i][0] = 0.f; acc[i][1] = 0.f; }

#pragma unroll
    for (int k4 = 0; k4 < 16; k4++) {
        float4 xv[8];
#pragma unroll
        for (int i = 0; i < 8; i++) xv[i] = *(float4*)&x_sm[ty * 8 + i][k4 * 4];
#pragma unroll
        for (int q = 0; q < 4; q++) {
            float2 wv = *(float2*)&wT[k4 * 4 + q][tx * 2];
#pragma unroll
            for (int i = 0; i < 8; i++) {
                float xs = (q == 0) ? xv[i].x : (q == 1) ? xv[i].y
                         : (q == 2) ? xv[i].z : xv[i].w;
                acc[i][0] += xs * wv.x;
                acc[i][1] += xs * wv.y;
            }
        }
    }

    int cbase = cb * 64 + tx * 2;
    int half = cbase >> 8, e = (cbase >> 6) & 3, f = cbase & 63;
#pragma unroll
    for (int i = 0; i < 8; i++) {
        int gr = rb * 64 + ty * 8 + i;
        int b = gr / 1000, n = gr % 1000;
        *(float2*)&g_s[half][b][e * 1000 + n][f] =
            make_float2(to_tf32(acc[i][0]), to_tf32(acc[i][1]));
    }
}

// ---------------------------------------------------------------------------
// Big adjacency GEMM on TF32 tensor cores, cp.async 3-stage pipeline:
//   a_half[b] (1000 x 64) = A_half[b] (1000 x 4000) @ s_half[b] (4000 x 64)
// grid (8, 2, 8), 256 threads (8 warps). CTA tile 128x64, warp tile 32x32.
// A smem stride 36, S stride 72 -> conflict-free fragment LDS.
// ---------------------------------------------------------------------------
#define ASTRIDE 36
#define SSTRIDE 72
#define A_STAGE (128 * ASTRIDE)
#define S_STAGE (32 * SSTRIDE)
#define SMEM_FLOATS (3 * A_STAGE + 3 * S_STAGE)

__global__ void __launch_bounds__(256) k_biggemm_tc2(const float* __restrict__ A) {
    extern __shared__ float smem[];
    float* a_base = smem;                    // [3][128][36]
    float* s_base = smem + 3 * A_STAGE;      // [3][32][72]

    int rb = blockIdx.x, half = blockIdx.y, b = blockIdx.z;
    int row0 = rb * 128;
    const float* Ab = A + (size_t)b * Nc * ACOLS + (size_t)half * NEc;
    const float* Sb = &g_s[half][b][0][0];

    int t = threadIdx.x;
    int lane = t & 31, warp = t >> 5;
    int g = lane >> 2, tg = lane & 3;
    int wm = warp >> 1, wn = warp & 1;

    unsigned smem_u = (unsigned)__cvta_generic_to_shared(smem);

    // cp.async per-thread source/dest (constant parts)
    const float* asrc[4]; unsigned adst[4];
#pragma unroll
    for (int c = 0; c < 4; c++) {
        int idx = c * 256 + t;
        int row = idx >> 3, part = idx & 7;
        int gr = row0 + row; if (gr > 999) gr = 999;
        asrc[c] = Ab + (size_t)gr * ACOLS + part * 4;
        adst[c] = (unsigned)(row * ASTRIDE + part * 4) * 4u;
    }
    const float* ssrc[2]; unsigned sdst[2];
#pragma unroll
    for (int c = 0; c < 2; c++) {
        int idx = c * 256 + t;
        int row = idx >> 4, part = idx & 15;
        ssrc[c] = Sb + (size_t)row * 64 + part * 4;
        sdst[c] = (unsigned)(3 * A_STAGE * 4) + (unsigned)(row * SSTRIDE + part * 4) * 4u;
    }

    float acc[2][4][4];
#pragma unroll
    for (int mt = 0; mt < 2; mt++)
#pragma unroll
        for (int nt = 0; nt < 4; nt++)
#pragma unroll
            for (int c = 0; c < 4; c++) acc[mt][nt][c] = 0.f;

    // ---- prologue: issue K tiles 0 and 1 ----
#pragma unroll
    for (int s = 0; s < 2; s++) {
        int kt = s * KT;
        unsigned ao = smem_u + (unsigned)(s * A_STAGE * 4);
        unsigned so = smem_u + (unsigned)(s * S_STAGE * 4);
#pragma unroll
        for (int c = 0; c < 4; c++) cp_async16(ao + adst[c], asrc[c] + kt);
#pragma unroll
        for (int c = 0; c < 2; c++) cp_async16(so + sdst[c], ssrc[c] + (size_t)kt * 64);
        cp_commit();
    }

    int stage = 0;
    for (int i = 0; i < NKT; i++) {
        cp_wait1();
        __syncthreads();

        // issue K tile i+2 into slot (i+2)%3 == (i-1)%3 (safe after the sync)
        if (i + 2 < NKT) {
            int s = (i + 2) % 3;
            int kt = (i + 2) * KT;
            unsigned ao = smem_u + (unsigned)(s * A_STAGE * 4);
            unsigned so = smem_u + (unsigned)(s * S_STAGE * 4);
#pragma unroll
            for (int c = 0; c < 4; c++) cp_async16(ao + adst[c], asrc[c] + kt);
#pragma unroll
            for (int c = 0; c < 2; c++) cp_async16(so + sdst[c], ssrc[c] + (size_t)kt * 64);
        }
        cp_commit();   // empty group when nothing issued keeps counting uniform

        // ---- compute on current stage ----
        const float* a_s = a_base + stage * A_STAGE;
        const float* s_s = s_base + stage * S_STAGE;
#pragma unroll
        for (int kk = 0; kk < 4; kk++) {
            unsigned af[2][4];
#pragma unroll
            for (int mt = 0; mt < 2; mt++) {
                int r0 = wm * 32 + mt * 16 + g;
                af[mt][0] = __float_as_uint(to_tf32(a_s[(r0)     * ASTRIDE + kk * 8 + tg]));
                af[mt][1] = __float_as_uint(to_tf32(a_s[(r0 + 8) * ASTRIDE + kk * 8 + tg]));
                af[mt][2] = __float_as_uint(to_tf32(a_s[(r0)     * ASTRIDE + kk * 8 + tg + 4]));
                af[mt][3] = __float_as_uint(to_tf32(a_s[(r0 + 8) * ASTRIDE + kk * 8 + tg + 4]));
            }
#pragma unroll
            for (int nt = 0; nt < 4; nt++) {
                int cn = wn * 32 + nt * 8 + g;
                unsigned b0 = __float_as_uint(s_s[(kk * 8 + tg)     * SSTRIDE + cn]);
                unsigned b1 = __float_as_uint(s_s[(kk * 8 + tg + 4) * SSTRIDE + cn]);
#pragma unroll
                for (int mt = 0; mt < 2; mt++) {
                    asm volatile(
                        "mma.sync.aligned.m16n8k8.row.col.f32.tf32.tf32.f32 "
                        "{%0,%1,%2,%3},{%4,%5,%6,%7},{%8,%9},{%0,%1,%2,%3};"
                        : "+f"(acc[mt][nt][0]), "+f"(acc[mt][nt][1]),
                          "+f"(acc[mt][nt][2]), "+f"(acc[mt][nt][3])
                        : "r"(af[mt][0]), "r"(af[mt][1]), "r"(af[mt][2]), "r"(af[mt][3]),
                          "r"(b0), "r"(b1));
                }
            }
        }
        stage = (stage + 1) % 3;
    }

    // ---- epilogue ----
    float(*C)[Dc] = g_a[half][b];
#pragma unroll
    for (int mt = 0; mt < 2; mt++) {
        int r_a = row0 + wm * 32 + mt * 16 + g;
        int r_b = r_a + 8;
#pragma unroll
        for (int nt = 0; nt < 4; nt++) {
            int col = wn * 32 + nt * 8 + tg * 2;
            if (r_a < Nc) *(float2*)&C[r_a][col] = make_float2(acc[mt][nt][0], acc[mt][nt][1]);
            if (r_b < Nc) *(float2*)&C[r_b][col] = make_float2(acc[mt][nt][2], acc[mt][nt][3]);
        }
    }
}

// ---------------------------------------------------------------------------
// GRU update. a = [a_in | a_out | state] (192)
// ---------------------------------------------------------------------------
__global__ void k_gru(const float* __restrict__ ext_state, int use_ext, int out_idx,
                      const float* __restrict__ W_r,
                      const float* __restrict__ W_z,
                      const float* __restrict__ W_h) {
    __shared__ float a_sm[16][192];
    __shared__ float rs_sm[16][64];
    int t = threadIdx.x;
    int base = blockIdx.x * 16;

#pragma unroll
    for (int c = 0; c < 3; c++) {
        int idx = c * 256 + t;
        int lr  = idx / 48;
        int j4  = idx % 48;
        int bn  = base + lr;
        int b = bn / Nc, n = bn % Nc;
        float4 v;
        if (j4 < 16)      v = *(const float4*)&g_a[0][b][n][j4 * 4];
        else if (j4 < 32) v = *(const float4*)&g_a[1][b][n][(j4 - 16) * 4];
        else {
            const float* sp = use_ext ? (ext_state + (size_t)bn * Dc)
                                      : &g_state[0][b][n][0];
            v = *(const float4*)&sp[(j4 - 32) * 4];
        }
        *(float4*)&a_sm[lr][j4 * 4] = v;
    }
    __syncthreads();

    int f = t & 63, q = t >> 6;
    const float4* Wr4 = (const float4*)(W_r + (size_t)f * 192);
    const float4* Wz4 = (const float4*)(W_z + (size_t)f * 192);
    const float4* Wh4 = (const float4*)(W_h + (size_t)f * 192);

    float pr[4] = {0, 0, 0, 0}, pz[4] = {0, 0, 0, 0}, h1[4] = {0, 0, 0, 0};

#pragma unroll 4
    for (int j4 = 0; j4 < 32; j4++) {
        float4 wr = Wr4[j4], wz = Wz4[j4], wh = Wh4[j4];
#pragma unroll
        for (int g = 0; g < 4; g++) {
            float4 av = *(float4*)&a_sm[q * 4 + g][j4 * 4];
            pr[g] += wr.x * av.x + wr.y * av.y + wr.z * av.z + wr.w * av.w;
            pz[g] += wz.x * av.x + wz.y * av.y + wz.z * av.z + wz.w * av.w;
            h1[g] += wh.x * av.x + wh.y * av.y + wh.z * av.z + wh.w * av.w;
        }
    }
#pragma unroll 4
    for (int j4 = 32; j4 < 48; j4++) {
        float4 wr = Wr4[j4], wz = Wz4[j4];
#pragma unroll
        for (int g = 0; g < 4; g++) {
            float4 av = *(float4*)&a_sm[q * 4 + g][j4 * 4];
            pr[g] += wr.x * av.x + wr.y * av.y + wr.z * av.z + wr.w * av.w;
            pz[g] += wz.x * av.x + wz.y * av.y + wz.z * av.z + wz.w * av.w;
        }
    }

#pragma unroll
    for (int g = 0; g < 4; g++) {
        float r = 1.f / (1.f + expf(-pr[g]));
        rs_sm[q * 4 + g][f] = r * a_sm[q * 4 + g][128 + f];
    }
    __syncthreads();

#pragma unroll 4
    for (int j4 = 0; j4 < 16; j4++) {
        float4 wh = Wh4[32 + j4];
#pragma unroll
        for (int g = 0; g < 4; g++) {
            float4 rv = *(float4*)&rs_sm[q * 4 + g][j4 * 4];
            h1[g] += wh.x * rv.x + wh.y * rv.y + wh.z * rv.z + wh.w * rv.w;
        }
    }

#pragma unroll
    for (int g = 0; g < 4; g++) {
        int lr = q * 4 + g;
        int bn = base + lr;
        int b = bn / Nc, n = bn % Nc;
        float st = a_sm[lr][128 + f];
        float z  = 1.f / (1.f + expf(-pz[g]));
        float h  = tanhf(h1[g]);
        g_state[out_idx][b][n][f] = (1.f - z) * st + z * h;
    }
}

// ---------------------------------------------------------------------------
// out[b,n] = sum_f tanh( sum_{j<96} [s2|annot][j] * Wo1[f,j] ) * Wo2[f]
// ---------------------------------------------------------------------------
__global__ void k_final(const float* __restrict__ annotation,
                        const float* __restrict__ Wo1,
                        const float* __restrict__ Wo2,
                        float* __restrict__ out) {
    __shared__ float join[4][96];
    __shared__ float terms[4][64];
    int t = threadIdx.x;
    int base = blockIdx.x * 4;

    for (int idx = t; idx < 4 * 96; idx += 256) {
        int lr = idx / 96, j = idx % 96;
        int bn = base + lr;
        int b = bn / Nc, n = bn % Nc;
        join[lr][j] = (j < Dc) ? g_state[1][b][n][j]
                               : annotation[(size_t)bn * ADc + (j - Dc)];
    }
    __syncthreads();

    int f = t & 63, q = t >> 6;
    const float4* w = (const float4*)(Wo1 + (size_t)f * 96);
    float acc = 0.f;
#pragma unroll
    for (int j4 = 0; j4 < 24; j4++) {
        float4 wv = w[j4];
        float4 jv = *(float4*)&join[q][j4 * 4];
        acc += wv.x * jv.x + wv.y * jv.y + wv.z * jv.z + wv.w * jv.w;
    }
    terms[q][f] = tanhf(acc) * Wo2[f];
    __syncthreads();

    if (f == 0) {
        float s = 0.f;
#pragma unroll
        for (int i = 0; i < Dc; i++) s += terms[q][i];
        out[base + q] = s;
    }
}

// ---------------------------------------------------------------------------
extern "C" void kernel_launch(void* const* d_in, const int* in_sizes, int n_in,
                              void* d_out, int out_size) {
    const float* prop_state = (const float*)d_in[0];
    const float* annotation = (const float*)d_in[1];
    const float* A          = (const float*)d_in[2];
    const float* W_in       = (const float*)d_in[3];
    const float* W_out      = (const float*)d_in[4];
    const float* W_r        = (const float*)d_in[5];
    const float* W_z        = (const float*)d_in[6];
    const float* W_h        = (const float*)d_in[7];
    const float* Wo1        = (const float*)d_in[8];
    const float* Wo2        = (const float*)d_in[9];
    float* out = (float*)d_out;

    static int smem_set = 0;
    int smem_bytes = SMEM_FLOATS * 4;
    if (!smem_set) {
        cudaFuncSetAttribute(k_biggemm_tc2,
                             cudaFuncAttributeMaxDynamicSharedMemorySize, smem_bytes);
        smem_set = 1;
    }

    dim3 s_grid(125, 8);
    dim3 gemm_grid(8, 2, Bc);

    // ---- propagate step 1 (state = prop_state) ----
    k_compute_s2<<<s_grid, 256>>>(prop_state, 1, W_in, W_out);
    k_biggemm_tc2<<<gemm_grid, 256, smem_bytes>>>(A);
    k_gru<<<Bc * Nc / 16, 256>>>(prop_state, 1, 0, W_r, W_z, W_h);

    // ---- propagate step 2 (state = g_state[0]) ----
    k_compute_s2<<<s_grid, 256>>>(nullptr, 0, W_in, W_out);
    k_biggemm_tc2<<<gemm_grid, 256, smem_bytes>>>(A);
    k_gru<<<Bc * Nc / 16, 256>>>(nullptr, 0, 1, W_r, W_z, W_h);

    // ---- output head ----
    k_final<<<Bc * Nc / 4, 256>>>(annotation, Wo1, Wo2, out);
}